// round 9
// baseline (speedup 1.0000x reference)
#include <cuda_runtime.h>
#include <math.h>

// Problem dims
#define Bsz   8
#define Ssz   2048
#define DMdim 512
#define Hh    8
#define SDdim 64
#define INNER 512
#define HID   2048
#define MROWS (Bsz*Ssz)   // 16384
#define NBH   64          // Bsz*Hh
#define CT    32          // scan chunk length
#define NCH   (Ssz/CT)    // 64 chunks

// ---------------- scratch (device globals: allocation-free) ----------------
__device__ float g_n [MROWS*DMdim];
__device__ float g_a [MROWS*INNER];
__device__ float g_b [MROWS*INNER];
__device__ float g_ql[MROWS*INNER];
__device__ float g_qr[MROWS*INNER];
__device__ float g_sd[MROWS*Hh];
__device__ float g_pd[MROWS*Hh];
__device__ float g_g [MROWS*INNER];
__device__ float g_r [MROWS*DMdim];
__device__ float g_l2[MROWS*DMdim];
__device__ float g_h [MROWS*HID];
__device__ float g_prev[MROWS*INNER];
__device__ float g_U [(size_t)NBH*NCH*SDdim*SDdim];   // 67 MB
__device__ float g_Dp[NBH*NCH*CT];

// ---------------- LayerNorm ----------------
__global__ __launch_bounds__(128)
void ln_kernel(const float* __restrict__ x, const float* __restrict__ gm,
               const float* __restrict__ bt, float* __restrict__ out)
{
    int row = blockIdx.x;
    int tid = threadIdx.x;
    const float4* xr = (const float4*)(x + (size_t)row * DMdim);
    float4 v = xr[tid];
    float s  = v.x + v.y + v.z + v.w;
    float s2 = v.x*v.x + v.y*v.y + v.z*v.z + v.w*v.w;
    #pragma unroll
    for (int o = 16; o > 0; o >>= 1) {
        s  += __shfl_xor_sync(0xffffffffu, s,  o);
        s2 += __shfl_xor_sync(0xffffffffu, s2, o);
    }
    __shared__ float ss[4], ss2[4];
    int wid = tid >> 5, lane = tid & 31;
    if (lane == 0) { ss[wid] = s; ss2[wid] = s2; }
    __syncthreads();
    s  = ss[0] + ss[1] + ss[2] + ss[3];
    s2 = ss2[0] + ss2[1] + ss2[2] + ss2[3];
    float m   = s * (1.0f / DMdim);
    float var = s2 * (1.0f / DMdim) - m * m;
    float inv = rsqrtf(var + 1e-5f);
    float4 gv = ((const float4*)gm)[tid];
    float4 bv = ((const float4*)bt)[tid];
    float4 o;
    o.x = (v.x - m) * inv * gv.x + bv.x;
    o.y = (v.y - m) * inv * gv.y + bv.y;
    o.z = (v.z - m) * inv * gv.z + bv.z;
    o.w = (v.w - m) * inv * gv.w + bv.w;
    ((float4*)(out + (size_t)row * DMdim))[tid] = o;
}

// ---------------- sd/pd gates ----------------
__global__ __launch_bounds__(512)
void sdpd_kernel(const float* __restrict__ n,
                 const float* __restrict__ Wsd, const float* __restrict__ bsd,
                 const float* __restrict__ Wpd, const float* __restrict__ bpd,
                 float* __restrict__ sd, float* __restrict__ pd)
{
    int row = blockIdx.x;
    __shared__ float nr[DMdim];
    int tid = threadIdx.x;
    nr[tid] = n[(size_t)row * DMdim + tid];
    __syncthreads();
    int w = tid >> 5, lane = tid & 31;
    const float* Wt = (w < 8) ? (Wsd + (size_t)w * DMdim) : (Wpd + (size_t)(w - 8) * DMdim);
    float acc = 0.f;
    #pragma unroll
    for (int j = lane; j < DMdim; j += 32) acc += nr[j] * Wt[j];
    #pragma unroll
    for (int o = 16; o > 0; o >>= 1) acc += __shfl_xor_sync(0xffffffffu, acc, o);
    if (lane == 0) {
        int h = w & 7;
        float bias = (w < 8) ? bsd[h] : bpd[h];
        float v = 1.f / (1.f + expf(-(acc + bias)));
        if (w < 8) sd[(size_t)row * Hh + h] = v;
        else       pd[(size_t)row * Hh + h] = v;
    }
}

// ---------------- tf32 tensor-core GEMM (unchanged from R6) ----------------
enum { EPI_TANH = 0, EPI_RES = 1, EPI_BIAS_GELU = 2, EPI_BIAS_RES = 3 };

#define ROWF   20
#define STAGEB (128*ROWF*4)
#define STAGES 4
#define GEMM_SMEM (STAGES*2*STAGEB)

__device__ __forceinline__ float fast_tanh(float x) {
    float y;
    asm("tanh.approx.f32 %0, %1;" : "=f"(y) : "f"(x));
    return y;
}
__device__ __forceinline__ void ldsm4(unsigned& r0, unsigned& r1,
                                      unsigned& r2, unsigned& r3, unsigned addr) {
    asm volatile("ldmatrix.sync.aligned.m8n8.x4.shared.b16 {%0,%1,%2,%3}, [%4];"
                 : "=r"(r0), "=r"(r1), "=r"(r2), "=r"(r3) : "r"(addr));
}

template<int EPI>
__global__ __launch_bounds__(256)
void mma_gemm_kernel(const float* __restrict__ A,
                     const float* __restrict__ w0, const float* __restrict__ w1,
                     const float* __restrict__ w2, const float* __restrict__ w3,
                     const float* __restrict__ bias, const float* __restrict__ resid,
                     float* c0, float* c1, float* c2, float* c3,
                     int N, int K)
{
    const int BK = 16;
    extern __shared__ __align__(16) float smem[];
    int z = blockIdx.z;
    const float* Bw = (z == 0) ? w0 : (z == 1) ? w1 : (z == 2) ? w2 : w3;
    float*       C  = (z == 0) ? c0 : (z == 1) ? c1 : (z == 2) ? c2 : c3;

    int tid  = threadIdx.x;
    int warp = tid >> 5, lane = tid & 31;
    int gq = lane >> 2, tg = lane & 3;
    int wm = warp & 3, wn = warp >> 2;
    int bn0 = blockIdx.x * 128, bm0 = blockIdx.y * 128;

    unsigned asA = (unsigned)__cvta_generic_to_shared(smem);
    unsigned asB = asA + STAGES * STAGEB;

    unsigned aAddr = asA + (unsigned)((wm * 32 + ((lane >> 3) & 1) * 8 + (lane & 7)) * ROWF
                                      + ((lane >> 4) & 1) * 4) * 4u;
    unsigned bAddr = asB + (unsigned)((wn * 64 + ((lane >> 4) & 1) * 8 + (lane & 7)) * ROWF
                                      + ((lane >> 3) & 1) * 4) * 4u;

    float acc[2][8][4];
    #pragma unroll
    for (int i = 0; i < 2; i++)
        #pragma unroll
        for (int j = 0; j < 8; j++)
            #pragma unroll
            for (int q = 0; q < 4; q++) acc[i][j][q] = 0.f;

    int cm = tid >> 2;
    int cc = (tid & 3) * 4;
    auto CPA = [&](int k0, int bf) {
        #pragma unroll
        for (int c = 0; c < 2; c++) {
            int m = cm + c * 64;
            unsigned da = asA + (unsigned)bf * STAGEB + (unsigned)(m * ROWF + cc) * 4u;
            const float* ga = A + (size_t)(bm0 + m) * K + k0 + cc;
            asm volatile("cp.async.cg.shared.global [%0], [%1], 16;" :: "r"(da), "l"(ga));
            unsigned db = asB + (unsigned)bf * STAGEB + (unsigned)(m * ROWF + cc) * 4u;
            const float* gb = Bw + (size_t)(bn0 + m) * K + k0 + cc;
            asm volatile("cp.async.cg.shared.global [%0], [%1], 16;" :: "r"(db), "l"(gb));
        }
        asm volatile("cp.async.commit_group;");
    };

    int NIT = K / BK;
    #pragma unroll
    for (int s = 0; s < STAGES - 1; s++) CPA(s * BK, s);

    int buf = 0;
    for (int it = 0; it < NIT; it++) {
        asm volatile("cp.async.wait_group %0;" :: "n"(STAGES - 2));
        __syncthreads();
        int nk = it + STAGES - 1;
        if (nk < NIT) CPA(nk * BK, nk & (STAGES - 1));

        unsigned bo = (unsigned)buf * STAGEB;
        #pragma unroll
        for (int s = 0; s < 2; s++) {
            unsigned so = s * 32u;
            unsigned af[2][4];
            #pragma unroll
            for (int i = 0; i < 2; i++)
                ldsm4(af[i][0], af[i][1], af[i][2], af[i][3],
                      aAddr + bo + so + (unsigned)(i * 16 * ROWF * 4));
            unsigned bfr[8][2];
            #pragma unroll
            for (int j2 = 0; j2 < 4; j2++) {
                unsigned r0, r1, r2, r3;
                ldsm4(r0, r1, r2, r3, bAddr + bo + so + (unsigned)(j2 * 16 * ROWF * 4));
                bfr[j2*2][0] = r0; bfr[j2*2][1] = r1;
                bfr[j2*2+1][0] = r2; bfr[j2*2+1][1] = r3;
            }
            #pragma unroll
            for (int i = 0; i < 2; i++)
                #pragma unroll
                for (int j = 0; j < 8; j++) {
                    asm volatile(
                        "mma.sync.aligned.m16n8k8.row.col.f32.tf32.tf32.f32 "
                        "{%0,%1,%2,%3}, {%4,%5,%6,%7}, {%8,%9}, {%0,%1,%2,%3};"
                        : "+f"(acc[i][j][0]), "+f"(acc[i][j][1]),
                          "+f"(acc[i][j][2]), "+f"(acc[i][j][3])
                        : "r"(af[i][0]), "r"(af[i][1]), "r"(af[i][2]), "r"(af[i][3]),
                          "r"(bfr[j][0]), "r"(bfr[j][1]));
                }
        }
        buf = (buf + 1) & (STAGES - 1);
    }

    #pragma unroll
    for (int i = 0; i < 2; i++) {
        int r0 = bm0 + wm * 32 + i * 16 + gq;
        #pragma unroll
        for (int j = 0; j < 8; j++) {
            int col = bn0 + wn * 64 + j * 8 + tg * 2;
            #pragma unroll
            for (int half = 0; half < 2; half++) {
                int row = r0 + half * 8;
                float v0 = acc[i][j][half * 2 + 0];
                float v1 = acc[i][j][half * 2 + 1];
                if (EPI == EPI_BIAS_GELU || EPI == EPI_BIAS_RES) {
                    v0 += bias[col]; v1 += bias[col + 1];
                }
                if (EPI == EPI_TANH) { v0 = fast_tanh(v0); v1 = fast_tanh(v1); }
                if (EPI == EPI_BIAS_GELU) {
                    v0 = 0.5f * v0 * (1.f + erff(v0 * 0.70710678118654752f));
                    v1 = 0.5f * v1 * (1.f + erff(v1 * 0.70710678118654752f));
                }
                if (EPI == EPI_RES || EPI == EPI_BIAS_RES) {
                    float2 rv = *(const float2*)(resid + (size_t)row * N + col);
                    v0 += rv.x; v1 += rv.y;
                }
                float2 o = {v0, v1};
                *(float2*)(C + (size_t)row * N + col) = o;
            }
        }
    }
}

// ================= scan stage 1: state scan -> prev_s = state_{s-1} =========
#define ST_PRE 8
__global__ __launch_bounds__(64)
void state_scan_kernel(const float* __restrict__ a, const float* __restrict__ sd,
                       float* __restrict__ prev)
{
    int bh = blockIdx.x;            // 0..63
    int d  = threadIdx.x;           // 0..63
    size_t base  = (size_t)(bh >> 3) * Ssz * INNER + (size_t)(bh & 7) * SDdim;
    size_t base8 = (size_t)(bh >> 3) * Ssz * Hh + (bh & 7);

    __shared__ float sa[2][ST_PRE][64];
    __shared__ float ssd[2][ST_PRE];

    int l0 = d * 4;        int r0 = l0 >> 6, c0 = l0 & 63;
    int l1 = 256 + d * 4;  int r1 = l1 >> 6, c1 = l1 & 63;
    float4 v0, v1; float vs = 0.f;

    auto LD = [&](int ch) {
        size_t bs = base + (size_t)ch * ST_PRE * INNER;
        v0 = *(const float4*)(a + bs + (size_t)r0 * INNER + c0);
        v1 = *(const float4*)(a + bs + (size_t)r1 * INNER + c1);
        if (d < ST_PRE) vs = sd[base8 + (size_t)(ch * ST_PRE + d) * Hh];
    };
    auto STm = [&](int bf) {
        *(float4*)&sa[bf][r0][c0] = v0;
        *(float4*)&sa[bf][r1][c1] = v1;
        if (d < ST_PRE) ssd[bf][d] = vs;
    };

    float st = 0.f;
    LD(0); STm(0); __syncthreads();
    const int NC = Ssz / ST_PRE;
    int buf = 0;
    size_t pbase = base + d;
    for (int ch = 0; ch < NC; ch++) {
        if (ch + 1 < NC) LD(ch + 1);
        #pragma unroll
        for (int t = 0; t < ST_PRE; t++) {
            prev[pbase] = st;                     // state BEFORE step t
            float sv = ssd[buf][t];
            st = sv * st + (1.f - sv) * sa[buf][t][d];
            pbase += INNER;
        }
        if (ch + 1 < NC) STm(buf ^ 1);
        __syncthreads();
        buf ^= 1;
    }
}

// ========= scan stage 2: intra-chunk attention + chunk summary U, Dpd =======
__global__ __launch_bounds__(256)
void chunk_attn_kernel(const float* __restrict__ prev, const float* __restrict__ bm,
                       const float* __restrict__ ql, const float* __restrict__ pd,
                       float* __restrict__ g, float* __restrict__ U,
                       float* __restrict__ Dp)
{
    int c   = blockIdx.x;   // chunk 0..63
    int bh  = blockIdx.y;   // 0..63
    int tid = threadIdx.x;

    __shared__ float qs[CT][68], ps[CT][68], bs[CT][68];
    __shared__ float w[CT][CT];
    __shared__ float pds[CT], coefs[CT], dpa[CT];

    size_t base  = (size_t)(bh >> 3) * Ssz * INNER + (size_t)(bh & 7) * SDdim
                 + (size_t)c * CT * INNER;
    size_t base8 = (size_t)(bh >> 3) * Ssz * Hh + (bh & 7) + (size_t)c * CT * Hh;

    {
        int l0 = tid * 4;        int r0 = l0 >> 6, q0 = l0 & 63;
        int l1 = 1024 + tid * 4; int r1 = l1 >> 6, q1 = l1 & 63;
        *(float4*)&qs[r0][q0] = *(const float4*)(ql   + base + (size_t)r0 * INNER + q0);
        *(float4*)&qs[r1][q1] = *(const float4*)(ql   + base + (size_t)r1 * INNER + q1);
        *(float4*)&ps[r0][q0] = *(const float4*)(prev + base + (size_t)r0 * INNER + q0);
        *(float4*)&ps[r1][q1] = *(const float4*)(prev + base + (size_t)r1 * INNER + q1);
        *(float4*)&bs[r0][q0] = *(const float4*)(bm   + base + (size_t)r0 * INNER + q0);
        *(float4*)&bs[r1][q1] = *(const float4*)(bm   + base + (size_t)r1 * INNER + q1);
        if (tid < CT) pds[tid] = pd[base8 + (size_t)tid * Hh];
    }
    __syncthreads();

    // decay weights: w[t][s] = (1-pd_s) * prod_{u=s+1..t} pd_u; dpa[t] = prod_{u<=t}
    if (tid < CT) {
        int t = tid;
        float dp = 1.f;
        for (int s = t; s >= 0; s--) {
            w[t][s] = (1.f - pds[s]) * dp;
            dp *= pds[s];
        }
        dpa[t] = dp;
        Dp[((size_t)bh * NCH + c) * CT + t] = dp;
    }
    __syncthreads();

    if (tid < CT) coefs[tid] = w[CT - 1][tid];   // coefficient into U (end-of-chunk)

    // raw scores: thread handles (t = tid>>3, s = (tid&7)*4 + j)
    int t  = tid >> 3;
    int s0 = (tid & 7) * 4;
    float sc[4] = {0.f, 0.f, 0.f, 0.f};
    if (s0 <= t) {
        for (int d4 = 0; d4 < 64; d4 += 4) {
            float4 qv = *(const float4*)&qs[t][d4];
            #pragma unroll
            for (int j = 0; j < 4; j++) {
                float4 pv = *(const float4*)&ps[s0 + j][d4];
                sc[j] += qv.x * pv.x + qv.y * pv.y + qv.z * pv.z + qv.w * pv.w;
            }
        }
    }
    __syncthreads();   // coefs copy done before w overwritten

    #pragma unroll
    for (int j = 0; j < 4; j++)
        if (s0 + j <= t) w[t][s0 + j] = sc[j] * w[t][s0 + j];
    __syncthreads();

    // lc_intra: thread (t2 = tid>>3, e-octet)
    {
        int t2 = tid >> 3, eo = (tid & 7) * 8;
        float acc[8] = {0,0,0,0,0,0,0,0};
        for (int s = 0; s <= t2; s++) {
            float wv = w[t2][s];
            float4 b0 = *(const float4*)&bs[s][eo];
            float4 b1 = *(const float4*)&bs[s][eo + 4];
            acc[0] += wv * b0.x; acc[1] += wv * b0.y;
            acc[2] += wv * b0.z; acc[3] += wv * b0.w;
            acc[4] += wv * b1.x; acc[5] += wv * b1.y;
            acc[6] += wv * b1.z; acc[7] += wv * b1.w;
        }
        float4 o0 = {acc[0], acc[1], acc[2], acc[3]};
        float4 o1 = {acc[4], acc[5], acc[6], acc[7]};
        *(float4*)(g + base + (size_t)t2 * INNER + eo)     = o0;
        *(float4*)(g + base + (size_t)t2 * INNER + eo + 4) = o1;
    }

    // U_c[d][e] = sum_s coefs[s] * prev_s[d] * b_s[e]
    {
        int du = tid >> 2, eq = (tid & 3) * 16;
        float au[16];
        #pragma unroll
        for (int k = 0; k < 16; k++) au[k] = 0.f;
        for (int s = 0; s < CT; s++) {
            float pv = coefs[s] * ps[s][du];
            #pragma unroll
            for (int k4 = 0; k4 < 4; k4++) {
                float4 bv = *(const float4*)&bs[s][eq + k4 * 4];
                au[k4*4+0] += pv * bv.x; au[k4*4+1] += pv * bv.y;
                au[k4*4+2] += pv * bv.z; au[k4*4+3] += pv * bv.w;
            }
        }
        float* Up = U + ((size_t)bh * NCH + c) * (SDdim * SDdim) + (size_t)du * SDdim + eq;
        #pragma unroll
        for (int k4 = 0; k4 < 4; k4++) {
            float4 o = {au[k4*4+0], au[k4*4+1], au[k4*4+2], au[k4*4+3]};
            *(float4*)(Up + k4 * 4) = o;
        }
    }
}

// ========= scan stage 3: sequential inter-chunk carry (P), finalize g =======
__global__ __launch_bounds__(256)
void carry_kernel(const float* __restrict__ ql, const float* __restrict__ qr,
                  const float* __restrict__ U, const float* __restrict__ Dp,
                  float* __restrict__ g)
{
    int blk = blockIdx.x;        // 128 = bh*2 + ehalf
    int eh  = blk & 1;
    int bh  = blk >> 1;
    int tid = threadIdx.x;

    __shared__ float P[64][36];  // [d][e-local 32], padded
    __shared__ float qs[CT][68];
    __shared__ float dpc[CT];

    for (int i = tid; i < 64 * 32; i += 256) P[i >> 5][i & 31] = 0.f;

    size_t base = (size_t)(bh >> 3) * Ssz * INNER + (size_t)(bh & 7) * SDdim;
    __syncthreads();

    for (int c = 0; c < NCH; c++) {
        size_t cb = base + (size_t)c * CT * INNER;
        {
            int l0 = tid * 4;        int r0 = l0 >> 6, q0 = l0 & 63;
            int l1 = 1024 + tid * 4; int r1 = l1 >> 6, q1 = l1 & 63;
            *(float4*)&qs[r0][q0] = *(const float4*)(ql + cb + (size_t)r0 * INNER + q0);
            *(float4*)&qs[r1][q1] = *(const float4*)(ql + cb + (size_t)r1 * INNER + q1);
            if (tid < CT) dpc[tid] = Dp[((size_t)bh * NCH + c) * CT + tid];
        }
        __syncthreads();

        // lc_inter[t][e] = dpc[t] * sum_d ql[t][d] * P[d][e]
        int t  = tid >> 3;
        int e4 = (tid & 7) * 4;                  // within e-half
        float acc[4] = {0.f, 0.f, 0.f, 0.f};
        for (int d = 0; d < 64; d++) {
            float qv = qs[t][d];
            float4 pv = *(const float4*)&P[d][e4];
            acc[0] += qv * pv.x; acc[1] += qv * pv.y;
            acc[2] += qv * pv.z; acc[3] += qv * pv.w;
        }
        float dpt = dpc[t];
        size_t gaddr = cb + (size_t)t * INNER + eh * 32 + e4;
        float4 gi = *(float4*)(g + gaddr);
        float4 qv4 = *(const float4*)(qr + gaddr);
        gi.x = (gi.x + dpt * acc[0]) * qv4.x;
        gi.y = (gi.y + dpt * acc[1]) * qv4.y;
        gi.z = (gi.z + dpt * acc[2]) * qv4.z;
        gi.w = (gi.w + dpt * acc[3]) * qv4.w;
        *(float4*)(g + gaddr) = gi;
        __syncthreads();                          // all P reads done

        // P = Dtot*P + U_c (e-half slice)
        float Dtot = dpc[CT - 1];
        const float* Up = U + ((size_t)bh * NCH + c) * (SDdim * SDdim) + eh * 32;
        int i0 = tid * 8;
        int d0 = i0 >> 5, e0 = i0 & 31;
        float4 u0 = *(const float4*)(Up + (size_t)d0 * SDdim + e0);
        float4 u1 = *(const float4*)(Up + (size_t)d0 * SDdim + e0 + 4);
        P[d0][e0 + 0] = Dtot * P[d0][e0 + 0] + u0.x;
        P[d0][e0 + 1] = Dtot * P[d0][e0 + 1] + u0.y;
        P[d0][e0 + 2] = Dtot * P[d0][e0 + 2] + u0.z;
        P[d0][e0 + 3] = Dtot * P[d0][e0 + 3] + u0.w;
        P[d0][e0 + 4] = Dtot * P[d0][e0 + 4] + u1.x;
        P[d0][e0 + 5] = Dtot * P[d0][e0 + 5] + u1.y;
        P[d0][e0 + 6] = Dtot * P[d0][e0 + 6] + u1.z;
        P[d0][e0 + 7] = Dtot * P[d0][e0 + 7] + u1.w;
        __syncthreads();
    }
}

// ---------------- launch ----------------
extern "C" void kernel_launch(void* const* d_in, const int* in_sizes, int n_in,
                              void* d_out, int out_size)
{
    const float* x    = (const float*)d_in[0];
    const float* ng   = (const float*)d_in[1];
    const float* nb   = (const float*)d_in[2];
    const float* fng  = (const float*)d_in[3];
    const float* fnb  = (const float*)d_in[4];
    const float* Wa   = (const float*)d_in[5];
    const float* Wb   = (const float*)d_in[6];
    const float* Wql  = (const float*)d_in[7];
    const float* Wqr  = (const float*)d_in[8];
    const float* Wsd  = (const float*)d_in[9];
    const float* bsd  = (const float*)d_in[10];
    const float* Wpd  = (const float*)d_in[11];
    const float* bpd  = (const float*)d_in[12];
    const float* Wout = (const float*)d_in[13];
    const float* W1   = (const float*)d_in[14];
    const float* b1   = (const float*)d_in[15];
    const float* W2   = (const float*)d_in[16];
    const float* b2   = (const float*)d_in[17];
    float* out = (float*)d_out;

    float *pn, *pa, *pb, *pql, *pqr, *psd, *ppd, *pg, *pr, *pl2, *ph;
    float *pprev, *pU, *pDp;
    cudaGetSymbolAddress((void**)&pn,  g_n);
    cudaGetSymbolAddress((void**)&pa,  g_a);
    cudaGetSymbolAddress((void**)&pb,  g_b);
    cudaGetSymbolAddress((void**)&pql, g_ql);
    cudaGetSymbolAddress((void**)&pqr, g_qr);
    cudaGetSymbolAddress((void**)&psd, g_sd);
    cudaGetSymbolAddress((void**)&ppd, g_pd);
    cudaGetSymbolAddress((void**)&pg,  g_g);
    cudaGetSymbolAddress((void**)&pr,  g_r);
    cudaGetSymbolAddress((void**)&pl2, g_l2);
    cudaGetSymbolAddress((void**)&ph,  g_h);
    cudaGetSymbolAddress((void**)&pprev, g_prev);
    cudaGetSymbolAddress((void**)&pU,  g_U);
    cudaGetSymbolAddress((void**)&pDp, g_Dp);

    cudaFuncSetAttribute(mma_gemm_kernel<EPI_TANH>,
                         cudaFuncAttributeMaxDynamicSharedMemorySize, GEMM_SMEM);
    cudaFuncSetAttribute(mma_gemm_kernel<EPI_RES>,
                         cudaFuncAttributeMaxDynamicSharedMemorySize, GEMM_SMEM);
    cudaFuncSetAttribute(mma_gemm_kernel<EPI_BIAS_GELU>,
                         cudaFuncAttributeMaxDynamicSharedMemorySize, GEMM_SMEM);
    cudaFuncSetAttribute(mma_gemm_kernel<EPI_BIAS_RES>,
                         cudaFuncAttributeMaxDynamicSharedMemorySize, GEMM_SMEM);

    // 1) n = LN(x)
    ln_kernel<<<MROWS, 128>>>(x, ng, nb, pn);

    // 2) fused tanh projections
    dim3 gp(INNER / 128, MROWS / 128, 4);
    mma_gemm_kernel<EPI_TANH><<<gp, 256, GEMM_SMEM>>>(
        pn, Wa, Wb, Wql, Wqr, nullptr, nullptr, pa, pb, pql, pqr, INNER, DMdim);

    // 3) sigmoid gates
    sdpd_kernel<<<MROWS, 512>>>(pn, Wsd, bsd, Wpd, bpd, psd, ppd);

    // 4) scan (chunked linear attention)
    state_scan_kernel<<<NBH, 64>>>(pa, psd, pprev);
    chunk_attn_kernel<<<dim3(NCH, NBH), 256>>>(pprev, pb, pql, ppd, pg, pU, pDp);
    carry_kernel<<<NBH * 2, 256>>>(pql, pqr, pU, pDp, pg);

    // 5) r = x + g @ Wout^T
    mma_gemm_kernel<EPI_RES><<<dim3(DMdim / 128, MROWS / 128, 1), 256, GEMM_SMEM>>>(
        pg, Wout, Wout, Wout, Wout, nullptr, x, pr, pr, pr, pr, DMdim, INNER);

    // 6) ln2 = LN(r)
    ln_kernel<<<MROWS, 128>>>(pr, fng, fnb, pl2);

    // 7) h = gelu(ln2 @ W1^T + b1)
    mma_gemm_kernel<EPI_BIAS_GELU><<<dim3(HID / 128, MROWS / 128, 1), 256, GEMM_SMEM>>>(
        pl2, W1, W1, W1, W1, b1, nullptr, ph, ph, ph, ph, HID, DMdim);

    // 8) out = r + h @ W2^T + b2
    mma_gemm_kernel<EPI_BIAS_RES><<<dim3(DMdim / 128, MROWS / 128, 1), 256, GEMM_SMEM>>>(
        ph, W2, W2, W2, W2, b2, pr, out, out, out, out, DMdim, HID);
}